// round 16
// baseline (speedup 1.0000x reference)
#include <cuda_runtime.h>
#include <cuda_fp16.h>
#include <cstdint>
#include <cstddef>

#define SEQ   512
#define DIM   256
#define HID   1024
#define BATCH 128
#define KTOT  1280
#define TSTEP 512
#define COUT  10

#define NCTA  128
#define NTHR  1024
#define CH_K  128           // K-chunk per stage (fp16)
#define NCH   5             // chunks per stream (1 x-chunk + 4 h-chunks)

// smem layout (bytes): [32,160) bias, [1024, 82944) weights fp16, then 4 A buffers
#define SM_BIAS  32
#define SM_W     1024
#define W_BYTES  (32 * KTOT * 2)               // 81920 (32 n x 1280 k fp16)
#define SM_A     (SM_W + W_BYTES)              // 82944 (256B aligned)
#define A_BYTES  (BATCH * CH_K * 2)            // 32768
#define SMEM_BYTES (SM_A + 4 * A_BYTES)        // 214016

// ---------------- device scratch (no allocations allowed) ----------------
__device__ uint2    g_Wp[(size_t)NCTA * 4 * 80 * 32];   // packed fp16 B frags (10.5 MB)
__device__ __half   g_x2[(size_t)BATCH * SEQ * DIM];    // x pre-rounded to fp16 (32 MB)
__device__ float    g_bcat[4 * HID];                    // fused bias (fp32)
__device__ __half   g_h[2][BATCH * HID];                // double-buffered hidden (fp16)
__device__ unsigned g_bar;                              // init-barrier counter
__device__ unsigned g_grp[16];                          // per-8-CTA-group step counters

// ---------------- helpers ----------------
__device__ __forceinline__ float sig_f(float x) {
    float ax = fabsf(x);
    float e  = __expf(-ax);
    float s  = __fdividef(1.0f, 1.0f + e);
    return (x >= 0.0f) ? s : (1.0f - s);
}
__device__ __forceinline__ float tanh_f(float x) {
    float ax = fabsf(x);
    float e  = __expf(-2.0f * ax);
    float t  = __fdividef(1.0f - e, 1.0f + e);
    return copysignf(t, x);
}
__device__ __forceinline__ void spin_ge(const unsigned* p, unsigned target) {
    unsigned v;
    do {
        asm volatile("ld.global.acquire.gpu.u32 %0, [%1];" : "=r"(v) : "l"(p));
    } while (v < target);
}
__device__ __forceinline__ void grid_bar(unsigned target) {
    __syncthreads();
    if (threadIdx.x == 0) {
        __threadfence();
        atomicAdd(&g_bar, 1u);
        spin_ge(&g_bar, target);
    }
    __syncthreads();
}
__device__ __forceinline__ void mma_f16(float* c, const uint32_t* a, uint2 b) {
    asm volatile(
        "mma.sync.aligned.m16n8k16.row.col.f32.f16.f16.f32 "
        "{%0,%1,%2,%3}, {%4,%5,%6,%7}, {%8,%9}, {%0,%1,%2,%3};\n"
        : "+f"(c[0]), "+f"(c[1]), "+f"(c[2]), "+f"(c[3])
        : "r"(a[0]), "r"(a[1]), "r"(a[2]), "r"(a[3]), "r"(b.x), "r"(b.y));
}

// k-ordering: stream s, chunk c -> base global k (x chunk first, then h)
__device__ __host__ __forceinline__ int chunk_kbase(int s, int c) {
    return (c == 0) ? (s * 128) : (DIM + s * 512 + (c - 1) * 128);
}

// reduction-set word index with bank-conflict-free jj swizzle
__device__ __forceinline__ int rword(int gate, int row, int jj) {
    return gate * 1024 + row * 8 + (jj ^ (row & 4));
}

// ---------------- setup: pack W into fp16 mma-B fragment layout (RN) ----------------
__global__ void pack_kernel(
    const float* __restrict__ Wgx, const float* __restrict__ Wix,
    const float* __restrict__ Wfx, const float* __restrict__ Wox,
    const float* __restrict__ Wgh, const float* __restrict__ Wih,
    const float* __restrict__ Wfh, const float* __restrict__ Woh,
    const float* __restrict__ bg,  const float* __restrict__ bi,
    const float* __restrict__ bf_, const float* __restrict__ bo)
{
    unsigned idx = blockIdx.x * blockDim.x + threadIdx.x;
    if (idx == 0) g_bar = 0u;                  // reset barriers each replay
    if (idx < 16) g_grp[idx] = 0u;
    if (idx < 4u * HID) {
        int gate = idx >> 10, j = idx & (HID - 1);
        const float* bp = (gate == 0) ? bg : (gate == 1) ? bi : (gate == 2) ? bf_ : bo;
        g_bcat[idx] = bp[j];
    }
    const unsigned total = (unsigned)NCTA * 4u * 80u * 32u;
    if (idx >= total) return;

    int lane = idx & 31;
    unsigned rest = idx >> 5;
    int ks  = rest % 80;                       // global k16-step (stream-ordered)
    int gt  = rest / 80;                       // cta*4 + gate
    int cta  = gt >> 2;
    int gate = gt & 3;
    int j = cta * 8 + (lane >> 2);             // n = lane>>2 within gate's 8 cols

    int s  = ks / 40;
    int r2 = ks % 40;
    int c  = r2 >> 3;                          // chunk 0..4
    int kk = r2 & 7;                           // k16-step within chunk
    int k0 = chunk_kbase(s, c) + kk * 16 + 2 * (lane & 3);

    const float* Wx = (gate == 0) ? Wgx : (gate == 1) ? Wix : (gate == 2) ? Wfx : Wox;
    const float* Wh = (gate == 0) ? Wgh : (gate == 1) ? Wih : (gate == 2) ? Wfh : Woh;

    float v0, v1, v8, v9;
    if (k0 < DIM) {
        v0 = Wx[k0 * HID + j];        v1 = Wx[(k0 + 1) * HID + j];
        v8 = Wx[(k0 + 8) * HID + j];  v9 = Wx[(k0 + 9) * HID + j];
    } else {
        int kh = k0 - DIM;
        v0 = Wh[kh * HID + j];        v1 = Wh[(kh + 1) * HID + j];
        v8 = Wh[(kh + 8) * HID + j];  v9 = Wh[(kh + 9) * HID + j];
    }

    __half2 b0 = __floats2half2_rn(v0, v1);
    __half2 b1 = __floats2half2_rn(v8, v9);
    uint2 pk;
    pk.x = *(uint32_t*)&b0;
    pk.y = *(uint32_t*)&b1;
    g_Wp[idx] = pk;
}

__global__ void roundx_kernel(const float* __restrict__ x) {
    size_t n = (size_t)BATCH * SEQ * DIM;
    for (size_t i = (size_t)blockIdx.x * blockDim.x + threadIdx.x; i < n;
         i += (size_t)gridDim.x * blockDim.x)
        g_x2[i] = __float2half_rn(x[i]);
}

// ---------------- persistent LSTM kernel ----------------
__global__ void __launch_bounds__(NTHR, 1)
lstm_kernel(const float* __restrict__ Wph,
            const float* __restrict__ bp,
            float* __restrict__ out)
{
    extern __shared__ __align__(1024) char smem[];
    const uint32_t sbase = (uint32_t)__cvta_generic_to_shared(smem);
    float*  bias_sm = (float*)(smem + SM_BIAS);
    const uint2* wsu2 = (const uint2*)(smem + SM_W);
    const uint32_t* Au = (const uint32_t*)(smem + SM_A);   // word view of A region
    float*  red = (float*)(smem + SM_A);                    // sets live in bufs 1 & 3

    const int tid   = threadIdx.x;
    const int cta   = blockIdx.x;
    const int wid   = tid >> 5;
    const int lane  = tid & 31;
    const int s     = wid >> 4;                // stream 0/1
    const int w16   = wid & 15;
    const int mw    = w16 & 3;                 // m-row group (32 rows)
    const int ng    = (w16 >> 2) & 1;          // gate-pair group 0/1
    const int u     = w16 >> 3;                // within-chunk k64 half 0/1
    const int lk    = lane & 3;
    const int lg    = lane >> 2;

    // reduction sets: (s,u) -> words; s0 in buffer 1, s1 in buffer 3
    const int mySet = (s ? 24576 : 8192) + u * 4096;

    // staging: 512 threads per stream; thread stages 64B (4x16B) of one row
    const int st   = tid & 511;
    const int srow = st >> 2;                  // 0..127
    const int q16  = st & 3;                   // 32-halves slice within 128-k row

    // weight copy (once; persists), bias, zero h0
    {
        const uint4* src = (const uint4*)(g_Wp + (size_t)cta * (4 * 80 * 32));
        uint4* dst = (uint4*)(smem + SM_W);
        for (int i = tid; i < W_BYTES / 16; i += NTHR) dst[i] = src[i];
    }
    if (tid < 32)
        bias_sm[tid] = g_bcat[(tid >> 3) * HID + cta * 8 + (tid & 7)];
    for (int i = cta * NTHR + tid; i < BATCH * HID / 2; i += NCTA * NTHR)
        ((uint32_t*)g_h[0])[i] = 0u;
    __syncthreads();
    grid_bar(1u * NCTA);                       // full barrier once at start

    // per-thread persistent cell state: thread owns (row = tid>>3, jj = tid&7)
    float creg = 0.0f;
    const int grow = tid >> 3;
    const int gjj  = tid & 7;

    // A-fragment word offsets: block(kt) = u*8 + 2*kt; off for k-hi = off ^ 4
    const int e8 = lg;                         // lg = 0..7
    int off0[4];
    #pragma unroll
    for (int kt = 0; kt < 4; kt++)
        off0[kt] = (((u * 8 + 2 * kt) ^ e8) << 2) | lk;
    const int rw0 = (mw * 32 + lg) * 64;       // word base of row r (64 words/row)

    // weight frag base: gates {2ng, 2ng+1}, stream s, k64-half u
    const uint2* wbase = wsu2 + ((size_t)(2 * ng) * 80u + (size_t)s * 40u
                                 + (size_t)u * 4u) * 32u + lane;

    // stage chunk c of timestep tt into buffer bf of this stream
    auto stage = [&](int tt, int c, int bf, const __half* hin) {
        const int kgk = chunk_kbase(s, c) + q16 * 32;
        const __half* src = (kgk < DIM)
            ? g_x2 + ((size_t)srow * SEQ + (size_t)tt) * DIM + kgk
            : hin + (size_t)srow * HID + (kgk - DIM);
        const uint32_t dbase = sbase + SM_A
            + (uint32_t)((s * 2 + bf) * A_BYTES) + (uint32_t)srow * 256u;
        #pragma unroll
        for (int i = 0; i < 4; i++) {
            int b = q16 * 4 + i;               // 16B block 0..15
            asm volatile("cp.async.cg.shared.global [%0], [%1], 16;"
                         :: "r"(dbase + (uint32_t)((b ^ (srow & 7)) * 16)),
                            "l"(src + 8 * i) : "memory");
        }
        asm volatile("cp.async.commit_group;" ::: "memory");
    };

    stage(0, 0, 0, nullptr);                   // t=0 prologue (x chunk)

    for (int t = 0; t < TSTEP; t++) {
        float acc[2][2][4];                    // [gate][mtile][q]
        #pragma unroll
        for (int g = 0; g < 2; g++)
            #pragma unroll
            for (int m = 0; m < 2; m++)
                #pragma unroll
                for (int q = 0; q < 4; q++) acc[g][m][q] = 0.0f;

        const __half* hin = g_h[t & 1];

        for (int c = 0; c < NCH; c++) {
            asm volatile("cp.async.wait_group 0;" ::: "memory");

            // fine-grained producer wait: chunk c+1 reads h cols of 2 groups.
            // each of a group's 8 CTAs adds 1 per step -> finished step t-1
            // means counter >= 8*t. leader spins; named bar releases stream.
            if (c + 1 < NCH && (tid & 511) == 0 && t > 0) {
                const int g0 = s * 8 + c * 2;  // chunk c+1 -> groups g0, g0+1
                spin_ge(&g_grp[g0], 8u * (unsigned)t);
                spin_ge(&g_grp[g0 + 1], 8u * (unsigned)t);
            }
            asm volatile("bar.sync %0, 512;" :: "r"(1 + s) : "memory");

            if (c + 1 < NCH) stage(t, c + 1, (c + 1) & 1, hin);   // overlaps compute

            const uint32_t* Ab = Au + (s * 2 + (c & 1)) * 8192;
            const uint2*    wc = wbase + (size_t)(c * 8) * 32u;

            #pragma unroll
            for (int kt = 0; kt < 4; kt++) {
                const int o0 = off0[kt];
                const int o1 = o0 ^ 4;
                uint32_t a0[4], a1[4];
                a0[0] = Ab[rw0 + o0];
                a0[1] = Ab[rw0 + 512 + o0];
                a0[2] = Ab[rw0 + o1];
                a0[3] = Ab[rw0 + 512 + o1];
                a1[0] = Ab[rw0 + 1024 + o0];
                a1[1] = Ab[rw0 + 1536 + o0];
                a1[2] = Ab[rw0 + 1024 + o1];
                a1[3] = Ab[rw0 + 1536 + o1];

                uint2 bv0 = wc[(size_t)kt * 32u];
                uint2 bv1 = wc[(size_t)(80 * 32) + (size_t)kt * 32u];
                mma_f16(acc[0][0], a0, bv0);
                mma_f16(acc[0][1], a1, bv0);
                mma_f16(acc[1][0], a0, bv1);
                mma_f16(acc[1][1], a1, bv1);
            }
        }

        __syncthreads();                       // all compute done; all buffers idle

        // EARLY: stage next step's x chunk 0 into buffers 0/2 (no h dependency)
        if (t + 1 < TSTEP) stage(t + 1, 0, 0, nullptr);

        // single-phase dump: all 32 warps write their (s,u) set (STS.64 packed)
        {
            float* rb = red + mySet;
            #pragma unroll
            for (int g = 0; g < 2; g++) {
                const int gate = 2 * ng + g;
                #pragma unroll
                for (int m = 0; m < 2; m++) {
                    const int row0 = mw * 32 + m * 16 + lg;
                    *(float2*)&rb[rword(gate, row0, 2 * lk)]
                        = make_float2(acc[g][m][0], acc[g][m][1]);
                    *(float2*)&rb[rword(gate, row0 + 8, 2 * lk)]
                        = make_float2(acc[g][m][2], acc[g][m][3]);
                }
            }
        }
        __syncthreads();

        // gates: every thread finishes exactly 1 cell (row=grow, jj=gjj)
        {
            float z[4];
            #pragma unroll
            for (int gate = 0; gate < 4; gate++) {
                const int w = rword(gate, grow, gjj);
                z[gate] = red[8192 + w] + red[12288 + w]
                        + red[24576 + w] + red[28672 + w]
                        + bias_sm[gate * 8 + gjj];
            }
            float c2 = tanh_f(z[0]) * sig_f(z[1]) + creg * sig_f(z[2]);
            creg = c2;
            g_h[(t + 1) & 1][(size_t)grow * HID + cta * 8 + gjj]
                = __float2half_rn(tanh_f(c2) * sig_f(z[3]));
        }

        __syncthreads();                       // set reads done before bufs 1/3 re-staged
        if (tid == 0) {                        // release this CTA's h columns
            __threadfence();
            atomicAdd(&g_grp[cta >> 3], 1u);
        }
    }

    // wait for ALL groups' final h writes before projection (8 CTAs x TSTEP each)
    if (tid == 0)
        for (int g = 0; g < 16; g++) spin_ge(&g_grp[g], 8u * (unsigned)TSTEP);
    __syncthreads();

    // final projection: out = h_T @ W_ph + b_p (h_T in g_h[0], T even)
    const __half* hfin = g_h[0];
    const int gw = cta * 32 + wid;
    for (int e = gw; e < BATCH * COUT; e += NCTA * 32) {
        const int b  = e / COUT;
        const int cc = e - b * COUT;
        float sacc = 0.0f;
        for (int j = lane; j < HID; j += 32)
            sacc += __half2float(hfin[b * HID + j]) * Wph[j * COUT + cc];
        #pragma unroll
        for (int off = 16; off; off >>= 1)
            sacc += __shfl_down_sync(0xFFFFFFFFu, sacc, off);
        if (lane == 0) out[e] = sacc + bp[cc];
    }
}

// ---------------- launch ----------------
extern "C" void kernel_launch(void* const* d_in, const int* in_sizes, int n_in,
                              void* d_out, int out_size)
{
    const float* x = (const float*)d_in[0];
    const float *Wgx, *Wix, *Wfx, *Wox, *Wgh, *Wih, *Wfh, *Woh;
    const float *bg, *bi, *bf_, *bo, *Wph, *bp;

    if (in_sizes[2] == HID * HID) {   // setup_inputs dict order
        Wgx = (const float*)d_in[1];  Wgh = (const float*)d_in[2];  bg  = (const float*)d_in[3];
        Wix = (const float*)d_in[4];  Wih = (const float*)d_in[5];  bi  = (const float*)d_in[6];
        Wfx = (const float*)d_in[7];  Wfh = (const float*)d_in[8];  bf_ = (const float*)d_in[9];
        Wox = (const float*)d_in[10]; Woh = (const float*)d_in[11]; bo  = (const float*)d_in[12];
        Wph = (const float*)d_in[13]; bp  = (const float*)d_in[14];
    } else {                          // signature order
        Wgx = (const float*)d_in[1];  Wix = (const float*)d_in[2];
        Wfx = (const float*)d_in[3];  Wox = (const float*)d_in[4];
        Wgh = (const float*)d_in[5];  Wih = (const float*)d_in[6];
        Wfh = (const float*)d_in[7];  Woh = (const float*)d_in[8];
        bg  = (const float*)d_in[9];  bi  = (const float*)d_in[10];
        bf_ = (const float*)d_in[11]; bo  = (const float*)d_in[12];
        Wph = (const float*)d_in[13]; bp  = (const float*)d_in[14];
    }

    const unsigned total = (unsigned)NCTA * 4u * 80u * 32u;
    pack_kernel<<<(total + 255) / 256, 256>>>(Wgx, Wix, Wfx, Wox,
                                              Wgh, Wih, Wfh, Woh,
                                              bg, bi, bf_, bo);
    roundx_kernel<<<2048, 256>>>(x);

    static bool attr_set = false;
    if (!attr_set) {
        cudaFuncSetAttribute(lstm_kernel,
                             cudaFuncAttributeMaxDynamicSharedMemorySize,
                             SMEM_BYTES);
        attr_set = true;
    }
    lstm_kernel<<<NCTA, NTHR, SMEM_BYTES>>>(Wph, bp, (float*)d_out);
}

// round 17
// speedup vs baseline: 1.2033x; 1.2033x over previous
#include <cuda_runtime.h>
#include <cuda_fp16.h>
#include <cstdint>
#include <cstddef>

#define SEQ   512
#define DIM   256
#define HID   1024
#define BATCH 128
#define KTOT  1280
#define TSTEP 512
#define COUT  10

#define NCTA  128
#define NTHR  1024
#define CH_K  128           // K-chunk per stage (fp16)
#define NCH   5             // chunks per stream (1 x-chunk + 4 h-chunks)

// smem layout (bytes): [32,160) bias, [1024, 82944) weights fp16, then 4 A buffers
#define SM_BIAS  32
#define SM_W     1024
#define W_BYTES  (32 * KTOT * 2)               // 81920 (32 n x 1280 k fp16)
#define SM_A     (SM_W + W_BYTES)              // 82944 (256B aligned)
#define A_BYTES  (BATCH * CH_K * 2)            // 32768
#define SMEM_BYTES (SM_A + 4 * A_BYTES)        // 214016

// ---------------- device scratch (no allocations allowed) ----------------
__device__ uint2    g_Wp[(size_t)NCTA * 4 * 80 * 32];   // packed fp16 B frags (10.5 MB)
__device__ __half   g_x2[(size_t)BATCH * SEQ * DIM];    // x pre-rounded to fp16 (32 MB)
__device__ float    g_bcat[4 * HID];                    // fused bias (fp32)
__device__ __half   g_h[2][BATCH * HID];                // double-buffered hidden (fp16)
__device__ unsigned g_bar;                              // monotonic grid barrier

// ---------------- helpers ----------------
__device__ __forceinline__ float sig_f(float x) {
    float ax = fabsf(x);
    float e  = __expf(-ax);
    float s  = __fdividef(1.0f, 1.0f + e);
    return (x >= 0.0f) ? s : (1.0f - s);
}
__device__ __forceinline__ float tanh_f(float x) {
    float ax = fabsf(x);
    float e  = __expf(-2.0f * ax);
    float t  = __fdividef(1.0f - e, 1.0f + e);
    return copysignf(t, x);
}
__device__ __forceinline__ void spin_wait(unsigned target) {
    unsigned v;
    do {
        asm volatile("ld.global.acquire.gpu.u32 %0, [%1];" : "=r"(v) : "l"(&g_bar));
    } while (v < target);
}
__device__ __forceinline__ void grid_bar(unsigned target) {
    __syncthreads();
    if (threadIdx.x == 0) {
        __threadfence();
        atomicAdd(&g_bar, 1u);
        spin_wait(target);
    }
    __syncthreads();
}
__device__ __forceinline__ void mma_f16(float* c, const uint32_t* a, uint2 b) {
    asm volatile(
        "mma.sync.aligned.m16n8k16.row.col.f32.f16.f16.f32 "
        "{%0,%1,%2,%3}, {%4,%5,%6,%7}, {%8,%9}, {%0,%1,%2,%3};\n"
        : "+f"(c[0]), "+f"(c[1]), "+f"(c[2]), "+f"(c[3])
        : "r"(a[0]), "r"(a[1]), "r"(a[2]), "r"(a[3]), "r"(b.x), "r"(b.y));
}

// k-ordering: stream s, chunk c -> base global k (x chunk first, then h)
__device__ __host__ __forceinline__ int chunk_kbase(int s, int c) {
    return (c == 0) ? (s * 128) : (DIM + s * 512 + (c - 1) * 128);
}

// reduction-set word index with bank-conflict-free jj swizzle
__device__ __forceinline__ int rword(int gate, int row, int jj) {
    return gate * 1024 + row * 8 + (jj ^ (row & 4));
}

// ---------------- setup: pack W into fp16 mma-B fragment layout (RN) ----------------
__global__ void pack_kernel(
    const float* __restrict__ Wgx, const float* __restrict__ Wix,
    const float* __restrict__ Wfx, const float* __restrict__ Wox,
    const float* __restrict__ Wgh, const float* __restrict__ Wih,
    const float* __restrict__ Wfh, const float* __restrict__ Woh,
    const float* __restrict__ bg,  const float* __restrict__ bi,
    const float* __restrict__ bf_, const float* __restrict__ bo)
{
    unsigned idx = blockIdx.x * blockDim.x + threadIdx.x;
    if (idx == 0) g_bar = 0u;                  // reset barrier each replay
    if (idx < 4u * HID) {
        int gate = idx >> 10, j = idx & (HID - 1);
        const float* bp = (gate == 0) ? bg : (gate == 1) ? bi : (gate == 2) ? bf_ : bo;
        g_bcat[idx] = bp[j];
    }
    const unsigned total = (unsigned)NCTA * 4u * 80u * 32u;
    if (idx >= total) return;

    int lane = idx & 31;
    unsigned rest = idx >> 5;
    int ks  = rest % 80;                       // global k16-step (stream-ordered)
    int gt  = rest / 80;                       // cta*4 + gate
    int cta  = gt >> 2;
    int gate = gt & 3;
    int j = cta * 8 + (lane >> 2);             // n = lane>>2 within gate's 8 cols

    int s  = ks / 40;
    int r2 = ks % 40;
    int c  = r2 >> 3;                          // chunk 0..4
    int kk = r2 & 7;                           // k16-step within chunk
    int k0 = chunk_kbase(s, c) + kk * 16 + 2 * (lane & 3);

    const float* Wx = (gate == 0) ? Wgx : (gate == 1) ? Wix : (gate == 2) ? Wfx : Wox;
    const float* Wh = (gate == 0) ? Wgh : (gate == 1) ? Wih : (gate == 2) ? Wfh : Woh;

    float v0, v1, v8, v9;
    if (k0 < DIM) {
        v0 = Wx[k0 * HID + j];        v1 = Wx[(k0 + 1) * HID + j];
        v8 = Wx[(k0 + 8) * HID + j];  v9 = Wx[(k0 + 9) * HID + j];
    } else {
        int kh = k0 - DIM;
        v0 = Wh[kh * HID + j];        v1 = Wh[(kh + 1) * HID + j];
        v8 = Wh[(kh + 8) * HID + j];  v9 = Wh[(kh + 9) * HID + j];
    }

    __half2 b0 = __floats2half2_rn(v0, v1);
    __half2 b1 = __floats2half2_rn(v8, v9);
    uint2 pk;
    pk.x = *(uint32_t*)&b0;
    pk.y = *(uint32_t*)&b1;
    g_Wp[idx] = pk;
}

__global__ void roundx_kernel(const float* __restrict__ x) {
    size_t n = (size_t)BATCH * SEQ * DIM;
    for (size_t i = (size_t)blockIdx.x * blockDim.x + threadIdx.x; i < n;
         i += (size_t)gridDim.x * blockDim.x)
        g_x2[i] = __float2half_rn(x[i]);
}

// ---------------- persistent LSTM kernel ----------------
__global__ void __launch_bounds__(NTHR, 1)
lstm_kernel(const float* __restrict__ Wph,
            const float* __restrict__ bp,
            float* __restrict__ out)
{
    extern __shared__ __align__(1024) char smem[];
    const uint32_t sbase = (uint32_t)__cvta_generic_to_shared(smem);
    float*  bias_sm = (float*)(smem + SM_BIAS);
    const uint2* wsu2 = (const uint2*)(smem + SM_W);
    const uint32_t* Au = (const uint32_t*)(smem + SM_A);   // word view of A region
    float*  red = (float*)(smem + SM_A);                    // sets live in bufs 1 & 3

    const int tid   = threadIdx.x;
    const int cta   = blockIdx.x;
    const int wid   = tid >> 5;
    const int lane  = tid & 31;
    const int s     = wid >> 4;                // stream 0/1
    const int w16   = wid & 15;
    const int mw    = w16 & 3;                 // m-row group (32 rows)
    const int ng    = (w16 >> 2) & 1;          // gate-pair group 0/1
    const int u     = w16 >> 3;                // within-chunk k64 half 0/1
    const int lk    = lane & 3;
    const int lg    = lane >> 2;

    // reduction sets: (s,u) -> words; s0 in buffer 1, s1 in buffer 3
    const int mySet = (s ? 24576 : 8192) + u * 4096;

    // staging: 512 threads per stream; thread stages 64B (4x16B) of one row
    const int st   = tid & 511;
    const int srow = st >> 2;                  // 0..127
    const int q16  = st & 3;                   // 32-halves slice within 128-k row

    // weight copy (once; persists), bias, zero h0
    {
        const uint4* src = (const uint4*)(g_Wp + (size_t)cta * (4 * 80 * 32));
        uint4* dst = (uint4*)(smem + SM_W);
        for (int i = tid; i < W_BYTES / 16; i += NTHR) dst[i] = src[i];
    }
    if (tid < 32)
        bias_sm[tid] = g_bcat[(tid >> 3) * HID + cta * 8 + (tid & 7)];
    for (int i = cta * NTHR + tid; i < BATCH * HID / 2; i += NCTA * NTHR)
        ((uint32_t*)g_h[0])[i] = 0u;
    __syncthreads();
    grid_bar(1u * NCTA);                       // full barrier once at start

    // per-thread persistent cell state: thread owns (row = tid>>3, jj = tid&7)
    float creg = 0.0f;
    const int grow = tid >> 3;
    const int gjj  = tid & 7;

    // A-fragment word offsets: block(kt) = u*8 + 2*kt; off for k-hi = off ^ 4
    const int e8 = lg;                         // lg = 0..7
    int off0[4];
    #pragma unroll
    for (int kt = 0; kt < 4; kt++)
        off0[kt] = (((u * 8 + 2 * kt) ^ e8) << 2) | lk;
    const int rw0 = (mw * 32 + lg) * 64;       // word base of row r (64 words/row)

    // weight frag base: gates {2ng, 2ng+1}, stream s, k64-half u
    const uint2* wbase = wsu2 + ((size_t)(2 * ng) * 80u + (size_t)s * 40u
                                 + (size_t)u * 4u) * 32u + lane;

    // stage chunk c of timestep tt into buffer bf of this stream
    auto stage = [&](int tt, int c, int bf, const __half* hin) {
        const int kgk = chunk_kbase(s, c) + q16 * 32;
        const __half* src = (kgk < DIM)
            ? g_x2 + ((size_t)srow * SEQ + (size_t)tt) * DIM + kgk
            : hin + (size_t)srow * HID + (kgk - DIM);
        const uint32_t dbase = sbase + SM_A
            + (uint32_t)((s * 2 + bf) * A_BYTES) + (uint32_t)srow * 256u;
        #pragma unroll
        for (int i = 0; i < 4; i++) {
            int b = q16 * 4 + i;               // 16B block 0..15
            asm volatile("cp.async.cg.shared.global [%0], [%1], 16;"
                         :: "r"(dbase + (uint32_t)((b ^ (srow & 7)) * 16)),
                            "l"(src + 8 * i) : "memory");
        }
        asm volatile("cp.async.commit_group;" ::: "memory");
    };

    // compute MMAs for the chunk currently in buffer bufIdx (stream-relative c)
    auto compute = [&](int c, float acc[2][2][4]) {
        const uint32_t* Ab = Au + (s * 2 + (c & 1)) * 8192;
        const uint2*    wc = wbase + (size_t)(c * 8) * 32u;
        #pragma unroll
        for (int kt = 0; kt < 4; kt++) {
            const int o0 = off0[kt];
            const int o1 = o0 ^ 4;
            uint32_t a0[4], a1[4];
            a0[0] = Ab[rw0 + o0];
            a0[1] = Ab[rw0 + 512 + o0];
            a0[2] = Ab[rw0 + o1];
            a0[3] = Ab[rw0 + 512 + o1];
            a1[0] = Ab[rw0 + 1024 + o0];
            a1[1] = Ab[rw0 + 1536 + o0];
            a1[2] = Ab[rw0 + 1024 + o1];
            a1[3] = Ab[rw0 + 1536 + o1];

            uint2 bv0 = wc[(size_t)kt * 32u];
            uint2 bv1 = wc[(size_t)(80 * 32) + (size_t)kt * 32u];
            mma_f16(acc[0][0], a0, bv0);
            mma_f16(acc[0][1], a1, bv0);
            mma_f16(acc[1][0], a0, bv1);
            mma_f16(acc[1][1], a1, bv1);
        }
    };

    stage(0, 0, 0, nullptr);                   // t=0 prologue (x chunk)

    for (int t = 0; t < TSTEP; t++) {
        float acc[2][2][4];                    // [gate][mtile][q]
        #pragma unroll
        for (int g = 0; g < 2; g++)
            #pragma unroll
            for (int m = 0; m < 2; m++)
                #pragma unroll
                for (int q = 0; q < 4; q++) acc[g][m][q] = 0.0f;

        const __half* hin = g_h[t & 1];

        // ---- c = 0 (x chunk): compute FIRST, then the global h-skew wait ----
        asm volatile("cp.async.wait_group 0;" ::: "memory");
        asm volatile("bar.sync %0, 512;" :: "r"(1 + s) : "memory");
        compute(0, acc);                       // x compute hides the skew wait below

        if ((tid & 511) == 0) spin_wait((unsigned)(t + 1) * NCTA);
        asm volatile("bar.sync %0, 512;" :: "r"(1 + s) : "memory");
        stage(t, 1, 1, hin);

        // ---- c = 1..4 (h chunks) ----
        for (int c = 1; c < NCH; c++) {
            asm volatile("cp.async.wait_group 0;" ::: "memory");
            asm volatile("bar.sync %0, 512;" :: "r"(1 + s) : "memory");

            if (c + 1 < NCH) stage(t, c + 1, (c + 1) & 1, hin);   // overlaps compute

            compute(c, acc);
        }

        __syncthreads();                       // all compute done; all buffers idle

        // EARLY: stage next step's x chunk 0 into buffers 0/2 (no h dependency)
        if (t + 1 < TSTEP) stage(t + 1, 0, 0, nullptr);

        // single-phase dump: all 32 warps write their (s,u) set (STS.64 packed)
        {
            float* rb = red + mySet;
            #pragma unroll
            for (int g = 0; g < 2; g++) {
                const int gate = 2 * ng + g;
                #pragma unroll
                for (int m = 0; m < 2; m++) {
                    const int row0 = mw * 32 + m * 16 + lg;
                    *(float2*)&rb[rword(gate, row0, 2 * lk)]
                        = make_float2(acc[g][m][0], acc[g][m][1]);
                    *(float2*)&rb[rword(gate, row0 + 8, 2 * lk)]
                        = make_float2(acc[g][m][2], acc[g][m][3]);
                }
            }
        }
        __syncthreads();

        // gates: every thread finishes exactly 1 cell (row=grow, jj=gjj)
        {
            float z[4];
            #pragma unroll
            for (int gate = 0; gate < 4; gate++) {
                const int w = rword(gate, grow, gjj);
                z[gate] = red[8192 + w] + red[12288 + w]
                        + red[24576 + w] + red[28672 + w]
                        + bias_sm[gate * 8 + gjj];
            }
            float c2 = tanh_f(z[0]) * sig_f(z[1]) + creg * sig_f(z[2]);
            creg = c2;
            g_h[(t + 1) & 1][(size_t)grow * HID + cta * 8 + gjj]
                = __float2half_rn(tanh_f(c2) * sig_f(z[3]));
        }

        __syncthreads();                       // set reads done before bufs 1/3 re-staged
        if (tid == 0) {                        // arrive-only release of h writes
            __threadfence();
            atomicAdd(&g_bar, 1u);
        }
    }

    // wait for ALL CTAs' final h writes before projection
    if (tid == 0) spin_wait((unsigned)(TSTEP + 1) * NCTA);
    __syncthreads();

    // final projection: out = h_T @ W_ph + b_p (h_T in g_h[0], T even)
    const __half* hfin = g_h[0];
    const int gw = cta * 32 + wid;
    for (int e = gw; e < BATCH * COUT; e += NCTA * 32) {
        const int b  = e / COUT;
        const int cc = e - b * COUT;
        float sacc = 0.0f;
        for (int j = lane; j < HID; j += 32)
            sacc += __half2float(hfin[b * HID + j]) * Wph[j * COUT + cc];
        #pragma unroll
        for (int off = 16; off; off >>= 1)
            sacc += __shfl_down_sync(0xFFFFFFFFu, sacc, off);
        if (lane == 0) out[e] = sacc + bp[cc];
    }
}

// ---------------- launch ----------------
extern "C" void kernel_launch(void* const* d_in, const int* in_sizes, int n_in,
                              void* d_out, int out_size)
{
    const float* x = (const float*)d_in[0];
    const float *Wgx, *Wix, *Wfx, *Wox, *Wgh, *Wih, *Wfh, *Woh;
    const float *bg, *bi, *bf_, *bo, *Wph, *bp;

    if (in_sizes[2] == HID * HID) {   // setup_inputs dict order
        Wgx = (const float*)d_in[1];  Wgh = (const float*)d_in[2];  bg  = (const float*)d_in[3];
        Wix = (const float*)d_in[4];  Wih = (const float*)d_in[5];  bi  = (const float*)d_in[6];
        Wfx = (const float*)d_in[7];  Wfh = (const float*)d_in[8];  bf_ = (const float*)d_in[9];
        Wox = (const float*)d_in[10]; Woh = (const float*)d_in[11]; bo  = (const float*)d_in[12];
        Wph = (const float*)d_in[13]; bp  = (const float*)d_in[14];
    } else {                          // signature order
        Wgx = (const float*)d_in[1];  Wix = (const float*)d_in[2];
        Wfx = (const float*)d_in[3];  Wox = (const float*)d_in[4];
        Wgh = (const float*)d_in[5];  Wih = (const float*)d_in[6];
        Wfh = (const float*)d_in[7];  Woh = (const float*)d_in[8];
        bg  = (const float*)d_in[9];  bi  = (const float*)d_in[10];
        bf_ = (const float*)d_in[11]; bo  = (const float*)d_in[12];
        Wph = (const float*)d_in[13]; bp  = (const float*)d_in[14];
    }

    const unsigned total = (unsigned)NCTA * 4u * 80u * 32u;
    pack_kernel<<<(total + 255) / 256, 256>>>(Wgx, Wix, Wfx, Wox,
                                              Wgh, Wih, Wfh, Woh,
                                              bg, bi, bf_, bo);
    roundx_kernel<<<2048, 256>>>(x);

    static bool attr_set = false;
    if (!attr_set) {
        cudaFuncSetAttribute(lstm_kernel,
                             cudaFuncAttributeMaxDynamicSharedMemorySize,
                             SMEM_BYTES);
        attr_set = true;
    }
    lstm_kernel<<<NCTA, NTHR, SMEM_BYTES>>>(Wph, bp, (float*)d_out);
}